// round 7
// baseline (speedup 1.0000x reference)
#include <cuda_runtime.h>

// Problem constants (fixed: B=128, C=1024, N=512, NUM_CLASSES=1024)
#define BB 128
#define CC 1024
#define NN 512
#define NC 1024
#define MAXL 64   // padded body-list length; actual count ~20 avg, <45 max
#define INVM 24   // max rows sharing one head atom; mean 2
#define GRID 512  // single wave guaranteed (needs 4 CTAs/SM of 148)

#define SENT ((NN << 1) | 1)   // odd sentinel -> m = g_mt[NN][b] = 0 -> no effect on max

// ---- scratch (device globals; zero-init at load) ----
__device__ float    g_mt[NN + 1][BB];      // row NN stays 0 forever (sentinel row)
__device__ int      g_body_list[CC][MAXL]; // packed (n<<1)|isNeg, sentinel-padded
__device__ int      g_inv_list[NN][INVM];  // packed (c<<1)|isNeg
__device__ int      g_inv_cnt[NN];         // reset in phase 3 each run
__device__ float    g_bmin[CC][BB];        // body_min per (row, batch)
__device__ unsigned g_bar;                 // monotonic ticket counter (never reset)

// Grid-wide barrier, graph-replay safe (monotonic tickets, wrap-safe compare).
__device__ __forceinline__ void grid_sync()
{
    __threadfence();          // release: prior stores visible at L2
    __syncthreads();
    if (threadIdx.x == 0) {
        unsigned ticket = atomicAdd(&g_bar, 1u);
        unsigned target = ticket - (ticket % GRID) + GRID;
        while ((int)(*(volatile unsigned*)&g_bar - target) < 0) { }
    }
    __syncthreads();
    __threadfence();          // acquire side
}

// Body max for one 64-entry sentinel-padded list segment in smem.
__device__ __forceinline__ float body_min_of(const int* lst, int t)
{
    float a[8];
    #pragma unroll
    for (int j = 0; j < 8; j++) a[j] = 0.0f;

    #pragma unroll
    for (int k = 0; k < MAXL; k += 16) {
        if (lst[k] == SENT) break;       // fully padded chunk -> done
        #pragma unroll
        for (int j = 0; j < 16; j++) {
            int e = lst[k + j];
            float m = __ldcg(&g_mt[e >> 1][t]);     // e>>1 <= NN; row NN = 0
            float term = (e & 1) ? m : (1.0f - m);
            a[j & 7] = fmaxf(a[j & 7], term);
        }
    }
    float r0 = fmaxf(fmaxf(a[0], a[1]), fmaxf(a[2], a[3]));
    float r1 = fmaxf(fmaxf(a[4], a[5]), fmaxf(a[6], a[7]));
    return 1.0f - fmaxf(r0, r1);         // same op order as reference (1 - max)
}

// ============ Single fused kernel: grid = 512 x 128, one wave ============
__global__ void __launch_bounds__(128, 4) k_fused(
    const float* __restrict__ preds,
    const float* __restrict__ pos_head,
    const float* __restrict__ neg_head,
    const float* __restrict__ pos_body,
    const float* __restrict__ neg_body,
    const int*   __restrict__ atoms,     // jax downcasts int64 -> int32
    float*       __restrict__ out)
{
    const int cb = blockIdx.x;          // 0..511
    const int c0 = cb * 2, c1 = c0 + 1;
    const int t  = threadIdx.x;

    // ================= Phase 1: prep =================
    // front-batched independent loads (MLP 8)
    const float4 p0 = ((const float4*)(pos_body + c0 * NN))[t];
    const float4 q0 = ((const float4*)(neg_body + c0 * NN))[t];
    const float4 h0 = ((const float4*)(pos_head + c0 * NN))[t];
    const float4 g0 = ((const float4*)(neg_head + c0 * NN))[t];
    const float4 p1 = ((const float4*)(pos_body + c1 * NN))[t];
    const float4 q1 = ((const float4*)(neg_body + c1 * NN))[t];
    const float4 h1 = ((const float4*)(pos_head + c1 * NN))[t];
    const float4 g1 = ((const float4*)(neg_head + c1 * NN))[t];

    // preds -> out copy: 64 float4 per CTA (threads 0..63)
    if (t < 64)
        ((float4*)out)[cb * 64 + t] = ((const float4*)preds)[cb * 64 + t];

    // g_mt gather: row n = cb, thread t = batch b
    g_mt[cb][t] = preds[t * NC + (atoms[cb] & (NC - 1))];

    __shared__ int cnt0, cnt1;
    __shared__ int lst[2 * MAXL];
    if (t == 0) { cnt0 = 0; cnt1 = 0; }
    __syncthreads();

    const int n0 = t * 4;

    { // compact row c0 body
        int loc[8]; int ln = 0;
        if (p0.x > 0.5f) loc[ln++] = ((n0 + 0) << 1);
        if (p0.y > 0.5f) loc[ln++] = ((n0 + 1) << 1);
        if (p0.z > 0.5f) loc[ln++] = ((n0 + 2) << 1);
        if (p0.w > 0.5f) loc[ln++] = ((n0 + 3) << 1);
        if (q0.x > 0.5f) loc[ln++] = ((n0 + 0) << 1) | 1;
        if (q0.y > 0.5f) loc[ln++] = ((n0 + 1) << 1) | 1;
        if (q0.z > 0.5f) loc[ln++] = ((n0 + 2) << 1) | 1;
        if (q0.w > 0.5f) loc[ln++] = ((n0 + 3) << 1) | 1;
        if (ln) {
            int base = atomicAdd(&cnt0, ln);
            #pragma unroll
            for (int i = 0; i < 8; i++)
                if (i < ln && base + i < MAXL) g_body_list[c0][base + i] = loc[i];
        }
    }
    { // compact row c1 body
        int loc[8]; int ln = 0;
        if (p1.x > 0.5f) loc[ln++] = ((n0 + 0) << 1);
        if (p1.y > 0.5f) loc[ln++] = ((n0 + 1) << 1);
        if (p1.z > 0.5f) loc[ln++] = ((n0 + 2) << 1);
        if (p1.w > 0.5f) loc[ln++] = ((n0 + 3) << 1);
        if (q1.x > 0.5f) loc[ln++] = ((n0 + 0) << 1) | 1;
        if (q1.y > 0.5f) loc[ln++] = ((n0 + 1) << 1) | 1;
        if (q1.z > 0.5f) loc[ln++] = ((n0 + 2) << 1) | 1;
        if (q1.w > 0.5f) loc[ln++] = ((n0 + 3) << 1) | 1;
        if (ln) {
            int base = atomicAdd(&cnt1, ln);
            #pragma unroll
            for (int i = 0; i < 8; i++)
                if (i < ln && base + i < MAXL) g_body_list[c1][base + i] = loc[i];
        }
    }

    { // head entry row c0 (exactly one nonzero across pos/neg head)
        int hm = -1;
        if (h0.x > 0.5f) hm = ((n0 + 0) << 1);
        if (h0.y > 0.5f) hm = ((n0 + 1) << 1);
        if (h0.z > 0.5f) hm = ((n0 + 2) << 1);
        if (h0.w > 0.5f) hm = ((n0 + 3) << 1);
        if (g0.x > 0.5f) hm = ((n0 + 0) << 1) | 1;
        if (g0.y > 0.5f) hm = ((n0 + 1) << 1) | 1;
        if (g0.z > 0.5f) hm = ((n0 + 2) << 1) | 1;
        if (g0.w > 0.5f) hm = ((n0 + 3) << 1) | 1;
        if (hm >= 0) {
            int n = (hm >> 1) & (NN - 1);
            int s = atomicAdd(&g_inv_cnt[n], 1);
            if (s < INVM) g_inv_list[n][s] = (c0 << 1) | (hm & 1);
        }
    }
    { // head entry row c1
        int hm = -1;
        if (h1.x > 0.5f) hm = ((n0 + 0) << 1);
        if (h1.y > 0.5f) hm = ((n0 + 1) << 1);
        if (h1.z > 0.5f) hm = ((n0 + 2) << 1);
        if (h1.w > 0.5f) hm = ((n0 + 3) << 1);
        if (g1.x > 0.5f) hm = ((n0 + 0) << 1) | 1;
        if (g1.y > 0.5f) hm = ((n0 + 1) << 1) | 1;
        if (g1.z > 0.5f) hm = ((n0 + 2) << 1) | 1;
        if (g1.w > 0.5f) hm = ((n0 + 3) << 1) | 1;
        if (hm >= 0) {
            int n = (hm >> 1) & (NN - 1);
            int s = atomicAdd(&g_inv_cnt[n], 1);
            if (s < INVM) g_inv_list[n][s] = (c1 << 1) | (hm & 1);
        }
    }

    __syncthreads();
    // sentinel-pad both lists to MAXL
    if (t < MAXL && t >= cnt0) g_body_list[c0][t] = SENT;
    if (t < MAXL && t >= cnt1) g_body_list[c1][t] = SENT;

    grid_sync();   // g_mt + lists + inv complete grid-wide

    // ================= Phase 2: body_min for rows c0, c1 =================
    // rows c0,c1 are contiguous in g_body_list -> one coalesced 128-int load
    lst[t] = __ldcg(&g_body_list[c0][0] + t);
    __syncthreads();

    g_bmin[c0][t] = body_min_of(lst, t);
    g_bmin[c1][t] = body_min_of(lst + MAXL, t);

    grid_sync();   // all bmin visible

    // ================= Phase 3: finalize atom n = cb =================
    {
        const int n  = cb;
        const int cn = min(__ldcg(&g_inv_cnt[n]), INVM);   // uniform

        float lbmax = 0.0f, ubmax = 0.0f;    // reference maxes include zeros
        for (int i = 0; i < cn; i++) {
            const int ent  = __ldcg(&g_inv_list[n][i]);    // uniform
            const float bm = __ldcg(&g_bmin[(ent >> 1) & (CC - 1)][t]);  // coalesced
            if (ent & 1) ubmax = fmaxf(ubmax, bm);
            else         lbmax = fmaxf(lbmax, bm);
        }

        if (t == 0) g_inv_cnt[n] = 0;        // replay-safe reset

        if (cn > 0) {
            const float ub = 1.0f - ubmax;
            const float lo = fminf(lbmax, ub);
            const float hi = fmaxf(lbmax, ub);
            const float m  = __ldcg(&g_mt[n][t]);
            out[t * NC + (atoms[n] & (NC - 1))] = fmaxf(lo, fminf(hi, m));
        }
        // cn == 0: clamp is identity -> copied preds value is already correct
    }
}

extern "C" void kernel_launch(void* const* d_in, const int* in_sizes, int n_in,
                              void* d_out, int out_size)
{
    const float* preds    = (const float*)d_in[0];
    const float* pos_head = (const float*)d_in[1];
    const float* neg_head = (const float*)d_in[2];
    const float* pos_body = (const float*)d_in[3];
    const float* neg_body = (const float*)d_in[4];
    const int*   atoms    = (const int*)d_in[5];
    float* out = (float*)d_out;

    k_fused<<<GRID, 128>>>(preds, pos_head, neg_head, pos_body, neg_body, atoms, out);
}

// round 8
// speedup vs baseline: 1.0118x; 1.0118x over previous
#include <cuda_runtime.h>

// Problem constants (fixed: B=128, C=1024, N=512, NUM_CLASSES=1024)
#define BB 128
#define CC 1024
#define NN 512
#define NC 1024
#define MAXL 64   // padded body-list length; actual count ~20 avg, <45 max
#define INVM 24   // max rows sharing one head atom; mean 2
#define GRID 512  // single wave guaranteed (8 CTAs/SM possible at 64 regs; need 4)

#define SENT ((NN << 1) | 1)   // odd sentinel -> m = g_mt[NN][b] = 0 -> no effect on max

// ---- scratch (device globals; zero-init at load) ----
__device__ float    g_mt[NN + 1][BB];      // row NN stays 0 forever (sentinel row)
__device__ int      g_inv_list[NN][INVM];  // packed (c<<1)|isNeg
__device__ int      g_inv_cnt[NN];         // reset in phase 3 each run
__device__ float    g_bmin[CC][BB];        // body_min per (row, batch)
__device__ unsigned g_arrive;              // monotonic ticket counter (never reset)
__device__ unsigned g_release;             // monotonic release epoch (never reset)

// Grid-wide barrier, graph-replay safe. Arrive counter and release word are
// SEPARATE lines: pollers never touch the atomic target (R7's serialization bug).
__device__ __forceinline__ void grid_sync()
{
    __threadfence();          // release: this thread's prior stores visible at L2
    __syncthreads();          // all CTA threads have fenced
    if (threadIdx.x == 0) {
        unsigned ticket = atomicAdd(&g_arrive, 1u);
        unsigned target = ticket - (ticket % GRID) + GRID;
        if (ticket % GRID == GRID - 1) {
            *(volatile unsigned*)&g_release = target;    // last arriver releases
        } else {
            while ((int)(*(volatile unsigned*)&g_release - target) < 0)
                __nanosleep(64);
        }
    }
    __syncthreads();
    __threadfence();          // acquire side
}

// Body max for one 64-entry sentinel-padded list segment in smem.
__device__ __forceinline__ float body_min_of(const int* lst, int t)
{
    float a[8];
    #pragma unroll
    for (int j = 0; j < 8; j++) a[j] = 0.0f;

    #pragma unroll
    for (int k = 0; k < MAXL; k += 16) {
        if (lst[k] == SENT) break;       // fully padded chunk -> done
        #pragma unroll
        for (int j = 0; j < 16; j++) {
            int e = lst[k + j];
            float m = __ldcg(&g_mt[e >> 1][t]);     // e>>1 <= NN; row NN = 0
            float term = (e & 1) ? m : (1.0f - m);
            a[j & 7] = fmaxf(a[j & 7], term);
        }
    }
    float r0 = fmaxf(fmaxf(a[0], a[1]), fmaxf(a[2], a[3]));
    float r1 = fmaxf(fmaxf(a[4], a[5]), fmaxf(a[6], a[7]));
    return 1.0f - fmaxf(r0, r1);         // same op order as reference (1 - max)
}

// ============ Single fused kernel: grid = 512 x 128, one wave ============
__global__ void __launch_bounds__(128, 4) k_fused(
    const float* __restrict__ preds,
    const float* __restrict__ pos_head,
    const float* __restrict__ neg_head,
    const float* __restrict__ pos_body,
    const float* __restrict__ neg_body,
    const int*   __restrict__ atoms,     // jax downcasts int64 -> int32
    float*       __restrict__ out)
{
    const int cb = blockIdx.x;          // 0..511
    const int c0 = cb * 2, c1 = c0 + 1;
    const int t  = threadIdx.x;

    __shared__ int cnt0, cnt1;
    __shared__ int lst[2 * MAXL];       // body lists live ONLY in smem

    // ================= Phase 1: prep =================
    // front-batched independent loads (MLP 8)
    const float4 p0 = ((const float4*)(pos_body + c0 * NN))[t];
    const float4 q0 = ((const float4*)(neg_body + c0 * NN))[t];
    const float4 h0 = ((const float4*)(pos_head + c0 * NN))[t];
    const float4 g0 = ((const float4*)(neg_head + c0 * NN))[t];
    const float4 p1 = ((const float4*)(pos_body + c1 * NN))[t];
    const float4 q1 = ((const float4*)(neg_body + c1 * NN))[t];
    const float4 h1 = ((const float4*)(pos_head + c1 * NN))[t];
    const float4 g1 = ((const float4*)(neg_head + c1 * NN))[t];

    // preds -> out copy: 64 float4 per CTA (threads 0..63)
    if (t < 64)
        ((float4*)out)[cb * 64 + t] = ((const float4*)preds)[cb * 64 + t];

    // g_mt gather: row n = cb, thread t = batch b
    g_mt[cb][t] = preds[t * NC + (atoms[cb] & (NC - 1))];

    if (t == 0) { cnt0 = 0; cnt1 = 0; }
    __syncthreads();

    const int n0 = t * 4;

    { // compact row c0 body -> smem lst[0..]
        int loc[8]; int ln = 0;
        if (p0.x > 0.5f) loc[ln++] = ((n0 + 0) << 1);
        if (p0.y > 0.5f) loc[ln++] = ((n0 + 1) << 1);
        if (p0.z > 0.5f) loc[ln++] = ((n0 + 2) << 1);
        if (p0.w > 0.5f) loc[ln++] = ((n0 + 3) << 1);
        if (q0.x > 0.5f) loc[ln++] = ((n0 + 0) << 1) | 1;
        if (q0.y > 0.5f) loc[ln++] = ((n0 + 1) << 1) | 1;
        if (q0.z > 0.5f) loc[ln++] = ((n0 + 2) << 1) | 1;
        if (q0.w > 0.5f) loc[ln++] = ((n0 + 3) << 1) | 1;
        if (ln) {
            int base = atomicAdd(&cnt0, ln);
            #pragma unroll
            for (int i = 0; i < 8; i++)
                if (i < ln && base + i < MAXL) lst[base + i] = loc[i];
        }
    }
    { // compact row c1 body -> smem lst[MAXL..]
        int loc[8]; int ln = 0;
        if (p1.x > 0.5f) loc[ln++] = ((n0 + 0) << 1);
        if (p1.y > 0.5f) loc[ln++] = ((n0 + 1) << 1);
        if (p1.z > 0.5f) loc[ln++] = ((n0 + 2) << 1);
        if (p1.w > 0.5f) loc[ln++] = ((n0 + 3) << 1);
        if (q1.x > 0.5f) loc[ln++] = ((n0 + 0) << 1) | 1;
        if (q1.y > 0.5f) loc[ln++] = ((n0 + 1) << 1) | 1;
        if (q1.z > 0.5f) loc[ln++] = ((n0 + 2) << 1) | 1;
        if (q1.w > 0.5f) loc[ln++] = ((n0 + 3) << 1) | 1;
        if (ln) {
            int base = atomicAdd(&cnt1, ln);
            #pragma unroll
            for (int i = 0; i < 8; i++)
                if (i < ln && base + i < MAXL) lst[MAXL + base + i] = loc[i];
        }
    }

    { // head entry row c0 (exactly one nonzero across pos/neg head)
        int hm = -1;
        if (h0.x > 0.5f) hm = ((n0 + 0) << 1);
        if (h0.y > 0.5f) hm = ((n0 + 1) << 1);
        if (h0.z > 0.5f) hm = ((n0 + 2) << 1);
        if (h0.w > 0.5f) hm = ((n0 + 3) << 1);
        if (g0.x > 0.5f) hm = ((n0 + 0) << 1) | 1;
        if (g0.y > 0.5f) hm = ((n0 + 1) << 1) | 1;
        if (g0.z > 0.5f) hm = ((n0 + 2) << 1) | 1;
        if (g0.w > 0.5f) hm = ((n0 + 3) << 1) | 1;
        if (hm >= 0) {
            int n = (hm >> 1) & (NN - 1);
            int s = atomicAdd(&g_inv_cnt[n], 1);
            if (s < INVM) g_inv_list[n][s] = (c0 << 1) | (hm & 1);
        }
    }
    { // head entry row c1
        int hm = -1;
        if (h1.x > 0.5f) hm = ((n0 + 0) << 1);
        if (h1.y > 0.5f) hm = ((n0 + 1) << 1);
        if (h1.z > 0.5f) hm = ((n0 + 2) << 1);
        if (h1.w > 0.5f) hm = ((n0 + 3) << 1);
        if (g1.x > 0.5f) hm = ((n0 + 0) << 1) | 1;
        if (g1.y > 0.5f) hm = ((n0 + 1) << 1) | 1;
        if (g1.z > 0.5f) hm = ((n0 + 2) << 1) | 1;
        if (g1.w > 0.5f) hm = ((n0 + 3) << 1) | 1;
        if (hm >= 0) {
            int n = (hm >> 1) & (NN - 1);
            int s = atomicAdd(&g_inv_cnt[n], 1);
            if (s < INVM) g_inv_list[n][s] = (c1 << 1) | (hm & 1);
        }
    }

    __syncthreads();
    // sentinel-pad both smem lists to MAXL
    if (t < MAXL) {
        if (t >= cnt0) lst[t]        = SENT;
        if (t >= cnt1) lst[MAXL + t] = SENT;
    }

    grid_sync();   // g_mt + inv lists complete grid-wide (body lists are CTA-local)

    // ================= Phase 2: body_min for rows c0, c1 (lists in smem) =====
    g_bmin[c0][t] = body_min_of(lst, t);
    g_bmin[c1][t] = body_min_of(lst + MAXL, t);

    grid_sync();   // all bmin visible

    // ================= Phase 3: finalize atom n = cb =================
    {
        const int n  = cb;
        const int cn = min(__ldcg(&g_inv_cnt[n]), INVM);   // uniform

        float lbmax = 0.0f, ubmax = 0.0f;    // reference maxes include zeros
        for (int i = 0; i < cn; i++) {
            const int ent  = __ldcg(&g_inv_list[n][i]);    // uniform
            const float bm = __ldcg(&g_bmin[(ent >> 1) & (CC - 1)][t]);  // coalesced
            if (ent & 1) ubmax = fmaxf(ubmax, bm);
            else         lbmax = fmaxf(lbmax, bm);
        }

        if (t == 0) g_inv_cnt[n] = 0;        // replay-safe reset

        if (cn > 0) {
            const float ub = 1.0f - ubmax;
            const float lo = fminf(lbmax, ub);
            const float hi = fmaxf(lbmax, ub);
            const float m  = __ldcg(&g_mt[n][t]);
            out[t * NC + (atoms[n] & (NC - 1))] = fmaxf(lo, fminf(hi, m));
        }
        // cn == 0: clamp is identity -> copied preds value is already correct
    }
}

extern "C" void kernel_launch(void* const* d_in, const int* in_sizes, int n_in,
                              void* d_out, int out_size)
{
    const float* preds    = (const float*)d_in[0];
    const float* pos_head = (const float*)d_in[1];
    const float* neg_head = (const float*)d_in[2];
    const float* pos_body = (const float*)d_in[3];
    const float* neg_body = (const float*)d_in[4];
    const int*   atoms    = (const int*)d_in[5];
    float* out = (float*)d_out;

    k_fused<<<GRID, 128>>>(preds, pos_head, neg_head, pos_body, neg_body, atoms, out);
}

// round 9
// speedup vs baseline: 1.1366x; 1.1233x over previous
#include <cuda_runtime.h>

// Problem constants (fixed: B=128, C=1024, N=512, NUM_CLASSES=1024)
#define BB 128
#define CC 1024
#define NN 512
#define NC 1024
#define MAXL 64   // padded body-list length; actual count ~20 avg, <45 max
#define INVM 24   // max rows sharing one head atom; mean 2

#define SENT ((NN << 1) | 1)   // odd sentinel -> m = g_mt[NN][b] = 0 -> no effect on max

// ---- scratch (device globals; zero-init at load; counters self-reset) ----
__device__ float g_mt[NN + 1][BB];      // row NN stays 0 forever (sentinel row)
__device__ int   g_body_list[CC][MAXL]; // packed (n<<1)|isNeg, sentinel-padded to 64
__device__ int   g_inv_list[NN][INVM];  // packed (c<<1)|isNeg
__device__ int   g_inv_cnt[NN];         // reset by k_final
__device__ float g_bmin[CC][BB];        // body_min per (row, batch)

// ============ Kernel 1: prep ============
// grid = 512 CTAs x 128 threads; CTA cb handles rows c0=2cb, c1=2cb+1.
__global__ void __launch_bounds__(128) k_prep(
    const float* __restrict__ preds,
    const float* __restrict__ pos_head,
    const float* __restrict__ neg_head,
    const float* __restrict__ pos_body,
    const float* __restrict__ neg_body,
    const int*   __restrict__ atoms,     // jax downcasts int64 -> int32
    float*       __restrict__ out)
{
    const int cb = blockIdx.x;          // 0..511
    const int c0 = cb * 2, c1 = c0 + 1;
    const int t  = threadIdx.x;

    // ---- front-batched independent loads (MLP 8) ----
    const float4 p0 = ((const float4*)(pos_body + c0 * NN))[t];
    const float4 q0 = ((const float4*)(neg_body + c0 * NN))[t];
    const float4 h0 = ((const float4*)(pos_head + c0 * NN))[t];
    const float4 g0 = ((const float4*)(neg_head + c0 * NN))[t];
    const float4 p1 = ((const float4*)(pos_body + c1 * NN))[t];
    const float4 q1 = ((const float4*)(neg_body + c1 * NN))[t];
    const float4 h1 = ((const float4*)(pos_head + c1 * NN))[t];
    const float4 g1 = ((const float4*)(neg_head + c1 * NN))[t];

    // preds -> out copy: 64 float4 per CTA (threads 0..63)
    if (t < 64)
        ((float4*)out)[cb * 64 + t] = ((const float4*)preds)[cb * 64 + t];

    // g_mt gather: row n = cb (512 CTAs cover all atoms), thread t = batch b
    g_mt[cb][t] = preds[t * NC + (atoms[cb] & (NC - 1))];

    __shared__ int cnt0, cnt1;
    if (t == 0) { cnt0 = 0; cnt1 = 0; }
    __syncthreads();

    const int n0 = t * 4;

    { // compact row c0 body
        int loc[8]; int ln = 0;
        if (p0.x > 0.5f) loc[ln++] = ((n0 + 0) << 1);
        if (p0.y > 0.5f) loc[ln++] = ((n0 + 1) << 1);
        if (p0.z > 0.5f) loc[ln++] = ((n0 + 2) << 1);
        if (p0.w > 0.5f) loc[ln++] = ((n0 + 3) << 1);
        if (q0.x > 0.5f) loc[ln++] = ((n0 + 0) << 1) | 1;
        if (q0.y > 0.5f) loc[ln++] = ((n0 + 1) << 1) | 1;
        if (q0.z > 0.5f) loc[ln++] = ((n0 + 2) << 1) | 1;
        if (q0.w > 0.5f) loc[ln++] = ((n0 + 3) << 1) | 1;
        if (ln) {
            int base = atomicAdd(&cnt0, ln);
            #pragma unroll
            for (int i = 0; i < 8; i++)
                if (i < ln && base + i < MAXL) g_body_list[c0][base + i] = loc[i];
        }
    }
    { // compact row c1 body
        int loc[8]; int ln = 0;
        if (p1.x > 0.5f) loc[ln++] = ((n0 + 0) << 1);
        if (p1.y > 0.5f) loc[ln++] = ((n0 + 1) << 1);
        if (p1.z > 0.5f) loc[ln++] = ((n0 + 2) << 1);
        if (p1.w > 0.5f) loc[ln++] = ((n0 + 3) << 1);
        if (q1.x > 0.5f) loc[ln++] = ((n0 + 0) << 1) | 1;
        if (q1.y > 0.5f) loc[ln++] = ((n0 + 1) << 1) | 1;
        if (q1.z > 0.5f) loc[ln++] = ((n0 + 2) << 1) | 1;
        if (q1.w > 0.5f) loc[ln++] = ((n0 + 3) << 1) | 1;
        if (ln) {
            int base = atomicAdd(&cnt1, ln);
            #pragma unroll
            for (int i = 0; i < 8; i++)
                if (i < ln && base + i < MAXL) g_body_list[c1][base + i] = loc[i];
        }
    }

    { // head entry row c0 (exactly one nonzero across pos/neg head)
        int hm = -1;
        if (h0.x > 0.5f) hm = ((n0 + 0) << 1);
        if (h0.y > 0.5f) hm = ((n0 + 1) << 1);
        if (h0.z > 0.5f) hm = ((n0 + 2) << 1);
        if (h0.w > 0.5f) hm = ((n0 + 3) << 1);
        if (g0.x > 0.5f) hm = ((n0 + 0) << 1) | 1;
        if (g0.y > 0.5f) hm = ((n0 + 1) << 1) | 1;
        if (g0.z > 0.5f) hm = ((n0 + 2) << 1) | 1;
        if (g0.w > 0.5f) hm = ((n0 + 3) << 1) | 1;
        if (hm >= 0) {
            int n = (hm >> 1) & (NN - 1);
            int s = atomicAdd(&g_inv_cnt[n], 1);
            if (s < INVM) g_inv_list[n][s] = (c0 << 1) | (hm & 1);
        }
    }
    { // head entry row c1
        int hm = -1;
        if (h1.x > 0.5f) hm = ((n0 + 0) << 1);
        if (h1.y > 0.5f) hm = ((n0 + 1) << 1);
        if (h1.z > 0.5f) hm = ((n0 + 2) << 1);
        if (h1.w > 0.5f) hm = ((n0 + 3) << 1);
        if (g1.x > 0.5f) hm = ((n0 + 0) << 1) | 1;
        if (g1.y > 0.5f) hm = ((n0 + 1) << 1) | 1;
        if (g1.z > 0.5f) hm = ((n0 + 2) << 1) | 1;
        if (g1.w > 0.5f) hm = ((n0 + 3) << 1) | 1;
        if (hm >= 0) {
            int n = (hm >> 1) & (NN - 1);
            int s = atomicAdd(&g_inv_cnt[n], 1);
            if (s < INVM) g_inv_list[n][s] = (c1 << 1) | (hm & 1);
        }
    }

    __syncthreads();
    // sentinel-pad both lists to MAXL
    if (t < MAXL && t >= cnt0) g_body_list[c0][t] = SENT;
    if (t < MAXL && t >= cnt1) g_body_list[c1][t] = SENT;
}

// ============ Kernel 2: body_min for rows 2cb, 2cb+1 (PDL) ============
// grid = 512 CTAs x 128 threads (thread = b). Launched with programmatic
// stream serialization: starts during k_prep, waits via griddepsync.
__global__ void __launch_bounds__(128) k_bodymin()
{
    cudaGridDependencySynchronize();   // wait: k_prep writes visible

    const int cb = blockIdx.x;
    const int c0 = cb * 2, c1 = c0 + 1;
    const int t  = threadIdx.x;

    __shared__ int lst[2 * MAXL];
    // rows c0,c1 contiguous in g_body_list -> one coalesced 128-int load
    lst[t] = __ldcg(&g_body_list[c0][0] + t);
    __syncthreads();

    #pragma unroll 2
    for (int r = 0; r < 2; r++) {
        const int* L = lst + r * MAXL;
        float a[8];
        #pragma unroll
        for (int j = 0; j < 8; j++) a[j] = 0.0f;

        #pragma unroll
        for (int k = 0; k < MAXL; k += 16) {
            if (L[k] == SENT) break;          // fully padded chunk -> done
            #pragma unroll
            for (int j = 0; j < 16; j++) {
                int e = L[k + j];
                float m = __ldcg(&g_mt[e >> 1][t]);   // e>>1 <= NN; row NN = 0
                float term = (e & 1) ? m : (1.0f - m);
                a[j & 7] = fmaxf(a[j & 7], term);
            }
        }
        float r0 = fmaxf(fmaxf(a[0], a[1]), fmaxf(a[2], a[3]));
        float r1 = fmaxf(fmaxf(a[4], a[5]), fmaxf(a[6], a[7]));
        g_bmin[c0 + r][t] = 1.0f - fmaxf(r0, r1);  // same op order as reference
    }
}

// ============ Kernel 3: per-atom finalize (PDL) ============
// grid = NN CTAs x 128 threads (thread = b).
__global__ void __launch_bounds__(128) k_final(
    const int* __restrict__ atoms,
    float*     __restrict__ out)
{
    cudaGridDependencySynchronize();   // wait: k_bodymin writes visible

    const int n = blockIdx.x;
    const int t = threadIdx.x;

    const int cn = min(__ldcg(&g_inv_cnt[n]), INVM);   // uniform

    float lbmax = 0.0f, ubmax = 0.0f;         // reference maxes include zeros
    for (int i = 0; i < cn; i++) {
        const int ent  = __ldcg(&g_inv_list[n][i]);               // uniform
        const float bm = __ldcg(&g_bmin[(ent >> 1) & (CC - 1)][t]); // coalesced
        if (ent & 1) ubmax = fmaxf(ubmax, bm);
        else         lbmax = fmaxf(lbmax, bm);
    }

    if (t == 0) g_inv_cnt[n] = 0;   // replay-safe reset

    if (cn > 0) {
        const float ub = 1.0f - ubmax;
        const float lo = fminf(lbmax, ub);
        const float hi = fmaxf(lbmax, ub);
        const float m  = __ldcg(&g_mt[n][t]);
        out[t * NC + (atoms[n] & (NC - 1))] = fmaxf(lo, fminf(hi, m));
    }
    // cn == 0: clamp is identity -> copied preds value is already correct
}

extern "C" void kernel_launch(void* const* d_in, const int* in_sizes, int n_in,
                              void* d_out, int out_size)
{
    const float* preds    = (const float*)d_in[0];
    const float* pos_head = (const float*)d_in[1];
    const float* neg_head = (const float*)d_in[2];
    const float* pos_body = (const float*)d_in[3];
    const float* neg_body = (const float*)d_in[4];
    const int*   atoms    = (const int*)d_in[5];
    float* out = (float*)d_out;

    // Node 1: normal launch
    k_prep<<<NN, 128>>>(preds, pos_head, neg_head, pos_body, neg_body, atoms, out);

    // Nodes 2,3: programmatic dependent launch (overlap launch setup with
    // upstream execution; griddepsync inside provides the ordering).
    cudaLaunchAttribute attr[1];
    attr[0].id = cudaLaunchAttributeProgrammaticStreamSerialization;
    attr[0].val.programmaticStreamSerializationAllowed = 1;

    {
        cudaLaunchConfig_t cfg{};
        cfg.gridDim  = dim3(NN, 1, 1);
        cfg.blockDim = dim3(128, 1, 1);
        cfg.dynamicSmemBytes = 0;
        cfg.stream = 0;
        cfg.attrs = attr;
        cfg.numAttrs = 1;
        cudaLaunchKernelEx(&cfg, k_bodymin);
    }
    {
        cudaLaunchConfig_t cfg{};
        cfg.gridDim  = dim3(NN, 1, 1);
        cfg.blockDim = dim3(128, 1, 1);
        cfg.dynamicSmemBytes = 0;
        cfg.stream = 0;
        cfg.attrs = attr;
        cfg.numAttrs = 1;
        cudaLaunchKernelEx(&cfg, k_final, atoms, out);
    }
}